// round 10
// baseline (speedup 1.0000x reference)
#include <cuda_runtime.h>
#include <cuda_bf16.h>
#include <math.h>
#include <stdint.h>

// Problem constants
#define Dq   1024
#define Hh   16
#define HDq  64
#define Bq   2
#define Nq   1024
#define ROWS (Bq * Nq)          // 2048
#define OUT_FINAL (ROWS * Dq)   // 2097152

// ---------------------------------------------------------------------------
// Scratch (device globals — no allocation allowed)
// ---------------------------------------------------------------------------
__device__ float g_hbar[Bq * Dq];                 // column SUMS of h per batch
__device__ float g_beff[Hh * Bq * HDq];           // effective layer-1 bias
__device__ float g_outbias[Dq];                   // Wo @ b2
__device__ __nv_bfloat16 g_Ah[ROWS * Dq], g_Al[ROWS * Dq];    // h split
__device__ __nv_bfloat16 g_WxH[Dq * Dq], g_WxL[Dq * Dq];      // Weff  = W1a·Wv split
__device__ __nv_bfloat16 g_WyH[Dq * Dq], g_WyL[Dq * Dq];      // Weff2 = Wo·bd(W2) split
__device__ __nv_bfloat16 g_gH[ROWS * Dq], g_gL[ROWS * Dq];    // GELU output split

// ---------------------------------------------------------------------------
// Helpers (base-target instructions only: ldmatrix / mma.sync / cp.async)
// ---------------------------------------------------------------------------
__device__ __forceinline__ uint32_t smem_u32(const void* p) {
    uint32_t a;
    asm("{ .reg .u64 t; cvta.to.shared.u64 t, %1; cvt.u32.u64 %0, t; }"
        : "=r"(a) : "l"(p));
    return a;
}
#define SW128(o) ((o) ^ (((o) >> 3) & 0x70))

#define CP_ASYNC16(dst, src) \
    asm volatile("cp.async.cg.shared.global [%0], [%1], 16;" :: "r"(dst), "l"(src))
#define CP_COMMIT() asm volatile("cp.async.commit_group;")
#define CP_WAIT(n)  asm volatile("cp.async.wait_group %0;" :: "n"(n) : "memory")

__device__ __forceinline__ void ldsm_x4(uint32_t* r, uint32_t addr) {
    asm volatile("ldmatrix.sync.aligned.m8n8.x4.shared.b16 {%0,%1,%2,%3}, [%4];"
                 : "=r"(r[0]), "=r"(r[1]), "=r"(r[2]), "=r"(r[3]) : "r"(addr));
}

__device__ __forceinline__ void mma16816(float* c, const uint32_t* a, const uint32_t* b) {
    asm volatile(
        "mma.sync.aligned.m16n8k16.row.col.f32.bf16.bf16.f32 "
        "{%0,%1,%2,%3}, {%4,%5,%6,%7}, {%8,%9}, {%0,%1,%2,%3};"
        : "+f"(c[0]), "+f"(c[1]), "+f"(c[2]), "+f"(c[3])
        : "r"(a[0]), "r"(a[1]), "r"(a[2]), "r"(a[3]), "r"(b[0]), "r"(b[1]));
}

__device__ __forceinline__ void split4(float4 v, __nv_bfloat16* hi, __nv_bfloat16* lo,
                                       size_t i2) {
    __nv_bfloat16 h0 = __float2bfloat16(v.x);
    __nv_bfloat16 h1 = __float2bfloat16(v.y);
    __nv_bfloat16 h2 = __float2bfloat16(v.z);
    __nv_bfloat16 h3 = __float2bfloat16(v.w);
    __nv_bfloat16 l0 = __float2bfloat16(v.x - __bfloat162float(h0));
    __nv_bfloat16 l1 = __float2bfloat16(v.y - __bfloat162float(h1));
    __nv_bfloat16 l2 = __float2bfloat16(v.z - __bfloat162float(h2));
    __nv_bfloat16 l3 = __float2bfloat16(v.w - __bfloat162float(h3));
    __nv_bfloat162 p;
    p.x = h0; p.y = h1; ((__nv_bfloat162*)hi)[i2] = p;
    p.x = h2; p.y = h3; ((__nv_bfloat162*)hi)[i2 + 1] = p;
    p.x = l0; p.y = l1; ((__nv_bfloat162*)lo)[i2] = p;
    p.x = l2; p.y = l3; ((__nv_bfloat162*)lo)[i2 + 1] = p;
}

__device__ __forceinline__ float gelu_exact(float x) {
    return 0.5f * x * (1.0f + erff(x * 0.70710678118654752f));
}

// ---------------------------------------------------------------------------
// zero g_hbar (graph replays require re-zero each call)
// ---------------------------------------------------------------------------
__global__ void zero_hbar() {
    int t = blockIdx.x * 256 + threadIdx.x;
    if (t < Bq * Dq) g_hbar[t] = 0.0f;
}

// ---------------------------------------------------------------------------
// cvt_all: blocks [0,512): split h into bf16 hi/lo AND accumulate per-batch
//          column sums into g_hbar (block = 16 rows x 256 cols).
//          blocks [512,520): tail outputs (targets + strength).
// ---------------------------------------------------------------------------
__global__ void __launch_bounds__(256)
cvt_all(const float4* __restrict__ hx, const int* __restrict__ prev_idx,
        const float* __restrict__ chain_ratio, float* __restrict__ out) {
    int blk = blockIdx.x, tid = threadIdx.x;
    if (blk < 512) {
        __shared__ float4 s[256];           // [rg][c4]
        int br = blk >> 2, bc = blk & 3;    // 128 row-blocks x 4 col-blocks
        int rg = tid >> 6, c4 = tid & 63;   // 4 row-groups x 64 float4-cols
        int col4 = bc * 64 + c4;            // float4 column index (0..255)
        float4 sum = make_float4(0.f, 0.f, 0.f, 0.f);
#pragma unroll
        for (int rr = 0; rr < 4; rr++) {
            int row = br * 16 + rg * 4 + rr;
            size_t idx = (size_t)row * 256 + col4;
            float4 v = hx[idx];
            split4(v, g_Ah, g_Al, idx * 2);
            sum.x += v.x; sum.y += v.y; sum.z += v.z; sum.w += v.w;
        }
        s[rg * 64 + c4] = sum;
        __syncthreads();
        if (tid < 64) {
            float4 a = s[tid], b2 = s[64 + tid], c = s[128 + tid], d = s[192 + tid];
            float4 t = make_float4(a.x + b2.x + c.x + d.x, a.y + b2.y + c.y + d.y,
                                   a.z + b2.z + c.z + d.z, a.w + b2.w + c.w + d.w);
            int b = br >> 6;   // batch = (br*16) / 1024
            float* dst = &g_hbar[b * Dq + bc * 256 + tid * 4];
            atomicAdd(dst + 0, t.x); atomicAdd(dst + 1, t.y);
            atomicAdd(dst + 2, t.z); atomicAdd(dst + 3, t.w);
        }
    } else {
        int idx = (blk - 512) * 256 + tid;
        if (idx >= ROWS) return;
        int n = idx & (Nq - 1);
        float cr = *chain_ratio;
        float thr = floorf((float)Nq / (1.0f + expf(-cr)));
        int p = prev_idx[idx];
        p = min(max(p, 0), Nq - 1);
        float ft = ((float)n >= thr) ? (float)p : 511.0f;
        out[OUT_FINAL + idx] = ft;
        out[OUT_FINAL + ROWS + idx] = 511.0f;
        out[OUT_FINAL + 2 * ROWS + idx] = 1.0f - logf(1.0f / (float)Nq + 1e-8f);
    }
}

// ---------------------------------------------------------------------------
// prep2: all small precomputations (grid = 448 blocks x 256 threads)
//  [0,32)    : (h,b) -> mu = Wv@hbar/N ; beff = b1 + (W1b+W1c)@mu
//  [32,160)  : Weff  = W1a·Wv   (per head, 128-col chunks) -> bf16 hi/lo
//  [160,416) : Weff2 = Wo·blockdiag(W2) (per head, 64-row chunks) -> bf16 hi/lo
//  [416,448) : outbias = Wo @ b2
// ---------------------------------------------------------------------------
__global__ void __launch_bounds__(256)
prep2(const float* __restrict__ Wv, const float* __restrict__ fu_W1,
      const float* __restrict__ fu_b1, const float* __restrict__ fu_W2,
      const float* __restrict__ fu_b2, const float* __restrict__ Wo) {
    __shared__ float s1[8192];   // 32KB
    __shared__ float s2[4096];   // 16KB
    const int blk = blockIdx.x, t = threadIdx.x;

    if (blk < 32) {
        // ---- mu + beff ----
        const int h = blk >> 1, b = blk & 1;
        float* hbar_s = s1;          // 1024
        float* part = s2;            // 256
        float* mu_s = s2 + 256;      // 64
        const float inv = 1.0f / (float)Nq;
        for (int k = t; k < 1024; k += 256) hbar_s[k] = g_hbar[b * Dq + k] * inv;
        __syncthreads();
        {
            int ep = t & 63, q = t >> 6;
            const float* wr = Wv + ((size_t)(h * 64 + ep)) * Dq + q * 256;
            float p = 0.0f;
#pragma unroll 8
            for (int i = 0; i < 256; i++) p = fmaf(wr[i], hbar_s[q * 256 + i], p);
            part[q * 64 + ep] = p;
        }
        __syncthreads();
        if (t < 64) mu_s[t] = part[t] + part[64 + t] + part[128 + t] + part[192 + t];
        __syncthreads();
        if (t < 64) {
            const float* w = fu_W1 + ((size_t)(h * 64 + t)) * 192;
            float acc = fu_b1[h * 64 + t];
#pragma unroll 8
            for (int e2 = 0; e2 < 64; e2++)
                acc = fmaf(w[64 + e2] + w[128 + e2], mu_s[e2], acc);
            g_beff[blk * 64 + t] = acc;
        }
    } else if (blk < 160) {
        // ---- Weff = W1a @ Wv  (rows (h,e), cols d) ----
        const int id = blk - 32, h = id >> 3, ch = id & 7;
        float* Wv_s = s1;    // [64][128]
        float* W1a_s = s2;   // [64][64]
#pragma unroll
        for (int k = 0; k < 4; k++) {
            int i4 = t + k * 256;
            int e = i4 >> 4, e4 = (i4 & 15) * 4;
            *(float4*)&W1a_s[e * 64 + e4] =
                *(const float4*)&fu_W1[((size_t)(h * 64 + e)) * 192 + e4];
        }
#pragma unroll
        for (int k = 0; k < 8; k++) {
            int i4 = t + k * 256;
            int e2 = i4 >> 5, d4 = (i4 & 31) * 4;
            *(float4*)&Wv_s[e2 * 128 + d4] =
                *(const float4*)&Wv[((size_t)(h * 64 + e2)) * Dq + ch * 128 + d4];
        }
        __syncthreads();
        const int d4 = (t & 31) * 4, e0 = (t >> 5) * 8;
#pragma unroll
        for (int e = e0; e < e0 + 8; e++) {
            float4 acc = make_float4(0.f, 0.f, 0.f, 0.f);
#pragma unroll 8
            for (int e2 = 0; e2 < 64; e2++) {
                float w = W1a_s[e * 64 + e2];
                float4 v = *(const float4*)&Wv_s[e2 * 128 + d4];
                acc.x = fmaf(w, v.x, acc.x); acc.y = fmaf(w, v.y, acc.y);
                acc.z = fmaf(w, v.z, acc.z); acc.w = fmaf(w, v.w, acc.w);
            }
            size_t off = ((size_t)(h * 64 + e)) * Dq + ch * 128 + d4;
            split4(acc, g_WxH, g_WxL, off >> 1);
        }
    } else if (blk < 416) {
        // ---- Weff2[e, h*64+x] = sum_f Wo[e, h*64+f] * W2[h][f,x] ----
        const int id = blk - 160, h = id >> 4, rch = id & 15;
        float* Wo_s = s1;   // [64 e][64 f]
        float* W2_s = s2;   // [64 f][64 x]
#pragma unroll
        for (int k = 0; k < 4; k++) {
            int i4 = t + k * 256;
            int e = i4 >> 4, f4 = (i4 & 15) * 4;
            *(float4*)&Wo_s[e * 64 + f4] =
                *(const float4*)&Wo[((size_t)(rch * 64 + e)) * Dq + h * 64 + f4];
            *(float4*)&W2_s[e * 64 + f4] =
                *(const float4*)&fu_W2[((size_t)(h * 64 + e)) * 64 + f4];
        }
        __syncthreads();
        const int x4 = (t & 15) * 4, e0 = (t >> 4) * 4;
#pragma unroll
        for (int e = e0; e < e0 + 4; e++) {
            float4 acc = make_float4(0.f, 0.f, 0.f, 0.f);
#pragma unroll 8
            for (int f = 0; f < 64; f++) {
                float w = Wo_s[e * 64 + f];
                float4 v = *(const float4*)&W2_s[f * 64 + x4];
                acc.x = fmaf(w, v.x, acc.x); acc.y = fmaf(w, v.y, acc.y);
                acc.z = fmaf(w, v.z, acc.z); acc.w = fmaf(w, v.w, acc.w);
            }
            size_t off = ((size_t)(rch * 64 + e)) * Dq + h * 64 + x4;
            split4(acc, g_WyH, g_WyL, off >> 1);
        }
    } else {
        // ---- outbias = Wo @ b2 ----
        const int id = blk - 416;     // 0..31, 32 e-rows each
        float* b2s = s1;
        for (int k = t; k < 1024; k += 256) b2s[k] = fu_b2[k];
        __syncthreads();
        int e = id * 32 + (t >> 3), seg = t & 7;
        const float* wr = Wo + (size_t)e * Dq + seg * 128;
        float p = 0.0f;
#pragma unroll 8
        for (int i = 0; i < 128; i++) p = fmaf(wr[i], b2s[seg * 128 + i], p);
        p += __shfl_down_sync(0xFFFFFFFFu, p, 4, 8);
        p += __shfl_down_sync(0xFFFFFFFFu, p, 2, 8);
        p += __shfl_down_sync(0xFFFFFFFFu, p, 1, 8);
        if (seg == 0) g_outbias[e] = p;
    }
}

// ---------------------------------------------------------------------------
// HMMA bf16 split GEMM, folded K'=3072 (segments (Ah,Bh),(Al,Bh),(Ah,Bl)).
// CTA tile 128x128, BK=64, 128 threads (4 warps, 2x2 grid, 64x64 warp tiles
// — CUTLASS shape: minimal LDSM traffic, 64KB/kt vs tensor 1024cyc/kt).
// 4-stage cp.async pipeline (wait_group 2), 32 independent MMAs per ks.
// MODE 0: epilogue x+beff -> GELU -> bf16 hi/lo (gH,gL).   extra = beff
// MODE 1: epilogue +bias -> fp32 C.                         extra = outbias
// ---------------------------------------------------------------------------
#define G_STAGE 32768
#define G_SMEM  (4 * G_STAGE + 512)
#define NKT 48

__device__ __forceinline__ void load_tile(uint32_t stage,
                                          const __nv_bfloat16* __restrict__ Aseg,
                                          const __nv_bfloat16* __restrict__ Bseg,
                                          int bm, int bn, int kin, int tid) {
#pragma unroll
    for (int rep = 0; rep < 8; rep++) {
        int id = rep * 128 + tid;        // 0..1023
        int row = id >> 3, c = id & 7;
        uint32_t so = SW128((uint32_t)(row * 128 + c * 16));
        CP_ASYNC16(stage + so, Aseg + (size_t)(bm + row) * Dq + kin + c * 8);
        CP_ASYNC16(stage + 16384 + so, Bseg + (size_t)(bn + row) * Dq + kin + c * 8);
    }
}

template<int MODE>
__global__ void __launch_bounds__(128, 1)
gemm_hmma(const __nv_bfloat16* __restrict__ Ah, const __nv_bfloat16* __restrict__ Al,
          const __nv_bfloat16* __restrict__ Bh, const __nv_bfloat16* __restrict__ Bl,
          float* __restrict__ C, __nv_bfloat16* __restrict__ gH,
          __nv_bfloat16* __restrict__ gL, const float* __restrict__ extra) {
    extern __shared__ char sm[];
    const uint32_t smb = smem_u32(sm);
    float* sextra = (float*)(sm + 4 * G_STAGE);
    const int tid = threadIdx.x;
    const int warp = tid >> 5, lane = tid & 31;
    const int wm = warp >> 1, wn = warp & 1;
    const int bm = blockIdx.y * 128, bn = blockIdx.x * 128;

    if (MODE == 0) {
        int c = bn + tid;
        sextra[tid] = extra[((c >> 6) * 2 + (bm >> 10)) * 64 + (c & 63)];
    } else {
        sextra[tid] = extra[bn + tid];
    }

    const __nv_bfloat16* Asegs[3] = {Ah, Al, Ah};
    const __nv_bfloat16* Bsegs[3] = {Bh, Bh, Bl};

    float acc[4][8][4];
#pragma unroll
    for (int mt = 0; mt < 4; mt++)
#pragma unroll
        for (int nt = 0; nt < 8; nt++)
#pragma unroll
            for (int i = 0; i < 4; i++) acc[mt][nt][i] = 0.0f;

    uint32_t a_off[4], b_off[4];
#pragma unroll
    for (int mt = 0; mt < 4; mt++) {
        int row = wm * 64 + mt * 16 + (lane & 15);
        a_off[mt] = (uint32_t)(row * 128 + (lane >> 4) * 16);
    }
#pragma unroll
    for (int np = 0; np < 4; np++) {
        int n = wn * 64 + np * 16 + (lane >> 4) * 8 + (lane & 7);
        b_off[np] = (uint32_t)(n * 128 + ((lane >> 3) & 1) * 16);
    }

#pragma unroll
    for (int s = 0; s < 3; s++) {
        load_tile(smb + s * G_STAGE, Asegs[s >> 4], Bsegs[s >> 4], bm, bn, (s & 15) * 64, tid);
        CP_COMMIT();
    }

    for (int kt = 0; kt < NKT; kt++) {
        CP_WAIT(2);
        __syncthreads();
        if (kt + 3 < NKT) {
            int pk = kt + 3;
            load_tile(smb + (pk & 3) * G_STAGE, Asegs[pk >> 4], Bsegs[pk >> 4],
                      bm, bn, (pk & 15) * 64, tid);
        }
        CP_COMMIT();

        const uint32_t sA = smb + (kt & 3) * G_STAGE;
        const uint32_t sB = sA + 16384;
#pragma unroll
        for (int ks = 0; ks < 4; ks++) {
            const uint32_t ko = (uint32_t)(ks * 32);
            uint32_t af[4][4], bf[4][4];
#pragma unroll
            for (int mt = 0; mt < 4; mt++)
                ldsm_x4(af[mt], sA + SW128(a_off[mt] + ko));
#pragma unroll
            for (int np = 0; np < 4; np++)
                ldsm_x4(bf[np], sB + SW128(b_off[np] + ko));
#pragma unroll
            for (int mt = 0; mt < 4; mt++)
#pragma unroll
                for (int np = 0; np < 4; np++) {
                    mma16816(acc[mt][np * 2],     af[mt], &bf[np][0]);
                    mma16816(acc[mt][np * 2 + 1], af[mt], &bf[np][2]);
                }
        }
    }

    // Epilogue
#pragma unroll
    for (int mt = 0; mt < 4; mt++) {
        int row = bm + wm * 64 + mt * 16 + (lane >> 2);
#pragma unroll
        for (int nt = 0; nt < 8; nt++) {
            int col = bn + wn * 64 + nt * 8 + (lane & 3) * 2;
            float b0 = sextra[col - bn], b1 = sextra[col - bn + 1];
            if (MODE == 1) {
                *(float2*)&C[(size_t)row * Dq + col] =
                    make_float2(acc[mt][nt][0] + b0, acc[mt][nt][1] + b1);
                *(float2*)&C[(size_t)(row + 8) * Dq + col] =
                    make_float2(acc[mt][nt][2] + b0, acc[mt][nt][3] + b1);
            } else {
                float g0 = gelu_exact(acc[mt][nt][0] + b0);
                float g1 = gelu_exact(acc[mt][nt][1] + b1);
                float g2 = gelu_exact(acc[mt][nt][2] + b0);
                float g3 = gelu_exact(acc[mt][nt][3] + b1);
                __nv_bfloat16 h0 = __float2bfloat16(g0), h1 = __float2bfloat16(g1);
                __nv_bfloat16 h2 = __float2bfloat16(g2), h3 = __float2bfloat16(g3);
                __nv_bfloat162 p;
                size_t o0 = (size_t)row * Dq + col, o1 = (size_t)(row + 8) * Dq + col;
                p.x = h0; p.y = h1; *(__nv_bfloat162*)&gH[o0] = p;
                p.x = h2; p.y = h3; *(__nv_bfloat162*)&gH[o1] = p;
                p.x = __float2bfloat16(g0 - __bfloat162float(h0));
                p.y = __float2bfloat16(g1 - __bfloat162float(h1));
                *(__nv_bfloat162*)&gL[o0] = p;
                p.x = __float2bfloat16(g2 - __bfloat162float(h2));
                p.y = __float2bfloat16(g3 - __bfloat162float(h3));
                *(__nv_bfloat162*)&gL[o1] = p;
            }
        }
    }
}

// ---------------------------------------------------------------------------
extern "C" void kernel_launch(void* const* d_in, const int* in_sizes, int n_in,
                              void* d_out, int out_size) {
    const float* h_in     = (const float*)d_in[0];
    const int*   prev_idx = (const int*)d_in[1];
    // d_in[2..9] = fw/bw encoder weights: dead (softmax of broadcast scalar
    // logit is uniform), never read.
    const float* Wv    = (const float*)d_in[10];
    const float* fu_W1 = (const float*)d_in[11];
    const float* fu_b1 = (const float*)d_in[12];
    const float* fu_W2 = (const float*)d_in[13];
    const float* fu_b2 = (const float*)d_in[14];
    const float* Wo    = (const float*)d_in[15];
    const float* chain_ratio = (const float*)d_in[16];
    float* out = (float*)d_out;

    cudaFuncSetAttribute(gemm_hmma<0>, cudaFuncAttributeMaxDynamicSharedMemorySize, G_SMEM);
    cudaFuncSetAttribute(gemm_hmma<1>, cudaFuncAttributeMaxDynamicSharedMemorySize, G_SMEM);

    __nv_bfloat16 *Ah, *Al, *WxH, *WxL, *WyH, *WyL, *gH, *gL;
    float *beff, *outbias;
    cudaGetSymbolAddress((void**)&Ah,  g_Ah);
    cudaGetSymbolAddress((void**)&Al,  g_Al);
    cudaGetSymbolAddress((void**)&WxH, g_WxH);
    cudaGetSymbolAddress((void**)&WxL, g_WxL);
    cudaGetSymbolAddress((void**)&WyH, g_WyH);
    cudaGetSymbolAddress((void**)&WyL, g_WyL);
    cudaGetSymbolAddress((void**)&gH,  g_gH);
    cudaGetSymbolAddress((void**)&gL,  g_gL);
    cudaGetSymbolAddress((void**)&beff,    g_beff);
    cudaGetSymbolAddress((void**)&outbias, g_outbias);

    dim3 grid(Dq / 128, ROWS / 128);

    // 0) zero hbar accumulators (graph-replay safe)
    zero_hbar<<<8, 256>>>();

    // 1) split h to bf16 hi/lo + per-batch column sums + tail outputs
    cvt_all<<<520, 256>>>((const float4*)h_in, prev_idx, chain_ratio, out);

    // 2) all small precomputations: beff, Weff, Weff2, outbias
    prep2<<<448, 256>>>(Wv, fu_W1, fu_b1, fu_W2, fu_b2, Wo);

    // 3) g = GELU(h @ Weff^T + beff) -> bf16 hi/lo
    gemm_hmma<0><<<grid, 128, G_SMEM>>>(Ah, Al, WxH, WxL, nullptr, gH, gL, beff);

    // 4) out = g @ Weff2^T + outbias
    gemm_hmma<1><<<grid, 128, G_SMEM>>>(gH, gL, WyH, WyL, out, nullptr, nullptr, outbias);
}

// round 11
// speedup vs baseline: 1.8930x; 1.8930x over previous
#include <cuda_runtime.h>
#include <cuda_fp16.h>
#include <math.h>
#include <stdint.h>

// Problem constants
#define Dq   1024
#define Hh   16
#define HDq  64
#define Bq   2
#define Nq   1024
#define ROWS (Bq * Nq)          // 2048
#define OUT_FINAL (ROWS * Dq)   // 2097152

// ---------------------------------------------------------------------------
// Scratch (device globals — no allocation allowed)
// ---------------------------------------------------------------------------
__device__ float g_part[128 * Dq];                // per-rowblock column sums of h
__device__ float g_beff[Hh * Bq * HDq];           // effective layer-1 bias
__device__ float g_outbias[Dq];                   // Wo @ b2
__device__ __half g_Ah[ROWS * Dq], g_Al[ROWS * Dq];   // h split (fp16 hi/lo)
__device__ __half g_Wx[Dq * Dq];                      // Weff  = W1a·Wv (fp16)
__device__ __half g_Wy[Dq * Dq];                      // Weff2 = Wo·bd(W2) (fp16)
__device__ __half g_gH[ROWS * Dq], g_gL[ROWS * Dq];   // GELU output split

// ---------------------------------------------------------------------------
// Helpers (base-target instructions only: ldmatrix / mma.sync / cp.async)
// ---------------------------------------------------------------------------
__device__ __forceinline__ uint32_t smem_u32(const void* p) {
    uint32_t a;
    asm("{ .reg .u64 t; cvta.to.shared.u64 t, %1; cvt.u32.u64 %0, t; }"
        : "=r"(a) : "l"(p));
    return a;
}
#define SW128(o) ((o) ^ (((o) >> 3) & 0x70))

#define CP_ASYNC16(dst, src) \
    asm volatile("cp.async.cg.shared.global [%0], [%1], 16;" :: "r"(dst), "l"(src))
#define CP_COMMIT() asm volatile("cp.async.commit_group;")
#define CP_WAIT(n)  asm volatile("cp.async.wait_group %0;" :: "n"(n) : "memory")

__device__ __forceinline__ void ldsm_x4(uint32_t* r, uint32_t addr) {
    asm volatile("ldmatrix.sync.aligned.m8n8.x4.shared.b16 {%0,%1,%2,%3}, [%4];"
                 : "=r"(r[0]), "=r"(r[1]), "=r"(r[2]), "=r"(r[3]) : "r"(addr));
}

__device__ __forceinline__ void mma16816(float* c, const uint32_t* a, const uint32_t* b) {
    asm volatile(
        "mma.sync.aligned.m16n8k16.row.col.f32.f16.f16.f32 "
        "{%0,%1,%2,%3}, {%4,%5,%6,%7}, {%8,%9}, {%0,%1,%2,%3};"
        : "+f"(c[0]), "+f"(c[1]), "+f"(c[2]), "+f"(c[3])
        : "r"(a[0]), "r"(a[1]), "r"(a[2]), "r"(a[3]), "r"(b[0]), "r"(b[1]));
}

__device__ __forceinline__ void split4h(float4 v, __half* hi, __half* lo, size_t i2) {
    __half h0 = __float2half_rn(v.x);
    __half h1 = __float2half_rn(v.y);
    __half h2 = __float2half_rn(v.z);
    __half h3 = __float2half_rn(v.w);
    __half l0 = __float2half_rn(v.x - __half2float(h0));
    __half l1 = __float2half_rn(v.y - __half2float(h1));
    __half l2 = __float2half_rn(v.z - __half2float(h2));
    __half l3 = __float2half_rn(v.w - __half2float(h3));
    __half2 p;
    p.x = h0; p.y = h1; ((__half2*)hi)[i2] = p;
    p.x = h2; p.y = h3; ((__half2*)hi)[i2 + 1] = p;
    p.x = l0; p.y = l1; ((__half2*)lo)[i2] = p;
    p.x = l2; p.y = l3; ((__half2*)lo)[i2 + 1] = p;
}

__device__ __forceinline__ void store4h(float4 v, __half* hi, size_t i2) {
    __half2 p;
    p.x = __float2half_rn(v.x); p.y = __float2half_rn(v.y);
    ((__half2*)hi)[i2] = p;
    p.x = __float2half_rn(v.z); p.y = __float2half_rn(v.w);
    ((__half2*)hi)[i2 + 1] = p;
}

__device__ __forceinline__ float gelu_exact(float x) {
    return 0.5f * x * (1.0f + erff(x * 0.70710678118654752f));
}

// ---------------------------------------------------------------------------
// cvt_all: blocks [0,512): split h into fp16 hi/lo AND write per-rowblock
//          column partial sums to g_part (block = 16 rows x 256 cols, no atomics).
//          blocks [512,520): tail outputs (targets + strength).
// ---------------------------------------------------------------------------
__global__ void __launch_bounds__(256)
cvt_all(const float4* __restrict__ hx, const int* __restrict__ prev_idx,
        const float* __restrict__ chain_ratio, float* __restrict__ out) {
    int blk = blockIdx.x, tid = threadIdx.x;
    if (blk < 512) {
        __shared__ float4 s[256];           // [rg][c4]
        int br = blk >> 2, bc = blk & 3;    // 128 row-blocks x 4 col-blocks
        int rg = tid >> 6, c4 = tid & 63;   // 4 row-groups x 64 float4-cols
        int col4 = bc * 64 + c4;            // float4 column index (0..255)
        float4 sum = make_float4(0.f, 0.f, 0.f, 0.f);
#pragma unroll
        for (int rr = 0; rr < 4; rr++) {
            int row = br * 16 + rg * 4 + rr;
            size_t idx = (size_t)row * 256 + col4;
            float4 v = hx[idx];
            split4h(v, g_Ah, g_Al, idx * 2);
            sum.x += v.x; sum.y += v.y; sum.z += v.z; sum.w += v.w;
        }
        s[rg * 64 + c4] = sum;
        __syncthreads();
        if (tid < 64) {
            float4 a = s[tid], b2 = s[64 + tid], c = s[128 + tid], d = s[192 + tid];
            float4 t = make_float4(a.x + b2.x + c.x + d.x, a.y + b2.y + c.y + d.y,
                                   a.z + b2.z + c.z + d.z, a.w + b2.w + c.w + d.w);
            *(float4*)&g_part[br * Dq + bc * 256 + tid * 4] = t;
        }
    } else {
        int idx = (blk - 512) * 256 + tid;
        if (idx >= ROWS) return;
        int n = idx & (Nq - 1);
        float cr = *chain_ratio;
        float thr = floorf((float)Nq / (1.0f + expf(-cr)));
        int p = prev_idx[idx];
        p = min(max(p, 0), Nq - 1);
        float ft = ((float)n >= thr) ? (float)p : 511.0f;
        out[OUT_FINAL + idx] = ft;
        out[OUT_FINAL + ROWS + idx] = 511.0f;
        out[OUT_FINAL + 2 * ROWS + idx] = 1.0f - logf(1.0f / (float)Nq + 1e-8f);
    }
}

// ---------------------------------------------------------------------------
// prep2: all small precomputations (grid = 448 blocks x 256 threads)
//  [0,32)    : (h,b) -> hbar (reduce g_part); mu = Wv@hbar; beff = b1+(W1b+W1c)@mu
//  [32,160)  : Weff  = W1a·Wv   (per head, 128-col chunks) -> fp16
//  [160,416) : Weff2 = Wo·blockdiag(W2) (per head, 64-row chunks) -> fp16
//  [416,448) : outbias = Wo @ b2
// ---------------------------------------------------------------------------
__global__ void __launch_bounds__(256)
prep2(const float* __restrict__ Wv, const float* __restrict__ fu_W1,
      const float* __restrict__ fu_b1, const float* __restrict__ fu_W2,
      const float* __restrict__ fu_b2, const float* __restrict__ Wo) {
    __shared__ float s1[8192];   // 32KB
    __shared__ float s2[4096];   // 16KB
    const int blk = blockIdx.x, t = threadIdx.x;

    if (blk < 32) {
        // ---- hbar + mu + beff ----
        const int h = blk >> 1, b = blk & 1;
        float* hbar_s = s1;          // 1024
        float* part = s2;            // 256
        float* mu_s = s2 + 256;      // 64
        const float inv = 1.0f / (float)Nq;
        for (int k = t; k < 1024; k += 256) {
            float s = 0.0f;
#pragma unroll 8
            for (int br = 0; br < 64; br++)
                s += g_part[(b * 64 + br) * Dq + k];
            hbar_s[k] = s * inv;
        }
        __syncthreads();
        {
            int ep = t & 63, q = t >> 6;
            const float* wr = Wv + ((size_t)(h * 64 + ep)) * Dq + q * 256;
            float p = 0.0f;
#pragma unroll 8
            for (int i = 0; i < 256; i++) p = fmaf(wr[i], hbar_s[q * 256 + i], p);
            part[q * 64 + ep] = p;
        }
        __syncthreads();
        if (t < 64) mu_s[t] = part[t] + part[64 + t] + part[128 + t] + part[192 + t];
        __syncthreads();
        if (t < 64) {
            const float* w = fu_W1 + ((size_t)(h * 64 + t)) * 192;
            float acc = fu_b1[h * 64 + t];
#pragma unroll 8
            for (int e2 = 0; e2 < 64; e2++)
                acc = fmaf(w[64 + e2] + w[128 + e2], mu_s[e2], acc);
            g_beff[blk * 64 + t] = acc;
        }
    } else if (blk < 160) {
        // ---- Weff = W1a @ Wv  (rows (h,e), cols d) -> fp16 ----
        const int id = blk - 32, h = id >> 3, ch = id & 7;
        float* Wv_s = s1;    // [64][128]
        float* W1a_s = s2;   // [64][64]
#pragma unroll
        for (int k = 0; k < 4; k++) {
            int i4 = t + k * 256;
            int e = i4 >> 4, e4 = (i4 & 15) * 4;
            *(float4*)&W1a_s[e * 64 + e4] =
                *(const float4*)&fu_W1[((size_t)(h * 64 + e)) * 192 + e4];
        }
#pragma unroll
        for (int k = 0; k < 8; k++) {
            int i4 = t + k * 256;
            int e2 = i4 >> 5, d4 = (i4 & 31) * 4;
            *(float4*)&Wv_s[e2 * 128 + d4] =
                *(const float4*)&Wv[((size_t)(h * 64 + e2)) * Dq + ch * 128 + d4];
        }
        __syncthreads();
        const int d4 = (t & 31) * 4, e0 = (t >> 5) * 8;
#pragma unroll
        for (int e = e0; e < e0 + 8; e++) {
            float4 acc = make_float4(0.f, 0.f, 0.f, 0.f);
#pragma unroll 8
            for (int e2 = 0; e2 < 64; e2++) {
                float w = W1a_s[e * 64 + e2];
                float4 v = *(const float4*)&Wv_s[e2 * 128 + d4];
                acc.x = fmaf(w, v.x, acc.x); acc.y = fmaf(w, v.y, acc.y);
                acc.z = fmaf(w, v.z, acc.z); acc.w = fmaf(w, v.w, acc.w);
            }
            size_t off = ((size_t)(h * 64 + e)) * Dq + ch * 128 + d4;
            store4h(acc, g_Wx, off >> 1);
        }
    } else if (blk < 416) {
        // ---- Weff2[e, h*64+x] = sum_f Wo[e, h*64+f] * W2[h][f,x] -> fp16 ----
        const int id = blk - 160, h = id >> 4, rch = id & 15;
        float* Wo_s = s1;   // [64 e][64 f]
        float* W2_s = s2;   // [64 f][64 x]
#pragma unroll
        for (int k = 0; k < 4; k++) {
            int i4 = t + k * 256;
            int e = i4 >> 4, f4 = (i4 & 15) * 4;
            *(float4*)&Wo_s[e * 64 + f4] =
                *(const float4*)&Wo[((size_t)(rch * 64 + e)) * Dq + h * 64 + f4];
            *(float4*)&W2_s[e * 64 + f4] =
                *(const float4*)&fu_W2[((size_t)(h * 64 + e)) * 64 + f4];
        }
        __syncthreads();
        const int x4 = (t & 15) * 4, e0 = (t >> 4) * 4;
#pragma unroll
        for (int e = e0; e < e0 + 4; e++) {
            float4 acc = make_float4(0.f, 0.f, 0.f, 0.f);
#pragma unroll 8
            for (int f = 0; f < 64; f++) {
                float w = Wo_s[e * 64 + f];
                float4 v = *(const float4*)&W2_s[f * 64 + x4];
                acc.x = fmaf(w, v.x, acc.x); acc.y = fmaf(w, v.y, acc.y);
                acc.z = fmaf(w, v.z, acc.z); acc.w = fmaf(w, v.w, acc.w);
            }
            size_t off = ((size_t)(rch * 64 + e)) * Dq + h * 64 + x4;
            store4h(acc, g_Wy, off >> 1);
        }
    } else {
        // ---- outbias = Wo @ b2 ----
        const int id = blk - 416;     // 0..31, 32 e-rows each
        float* b2s = s1;
        for (int k = t; k < 1024; k += 256) b2s[k] = fu_b2[k];
        __syncthreads();
        int e = id * 32 + (t >> 3), seg = t & 7;
        const float* wr = Wo + (size_t)e * Dq + seg * 128;
        float p = 0.0f;
#pragma unroll 8
        for (int i = 0; i < 128; i++) p = fmaf(wr[i], b2s[seg * 128 + i], p);
        p += __shfl_down_sync(0xFFFFFFFFu, p, 4, 8);
        p += __shfl_down_sync(0xFFFFFFFFu, p, 2, 8);
        p += __shfl_down_sync(0xFFFFFFFFu, p, 1, 8);
        if (seg == 0) g_outbias[e] = p;
    }
}

// ---------------------------------------------------------------------------
// HMMA fp16 2-segment GEMM: C = Ah@B^T + Al@B^T (K'=2048).
// CTA tile 128x128, BK=64, 256 thr (8 warps, 4x2 grid, 32x64 warp tiles —
// best measured shape), 4-stage cp.async pipeline + intra-kt fragment DB.
// MODE 0: epilogue x+beff -> GELU -> fp16 hi/lo (gH,gL).   extra = beff
// MODE 1: epilogue +bias -> fp32 C.                         extra = outbias
// ---------------------------------------------------------------------------
#define G_STAGE 32768
#define G_SMEM  (4 * G_STAGE + 512)
#define NKT 32

__device__ __forceinline__ void load_tile(uint32_t stage,
                                          const __half* __restrict__ Aseg,
                                          const __half* __restrict__ Bseg,
                                          int bm, int bn, int kin, int tid) {
#pragma unroll
    for (int rep = 0; rep < 4; rep++) {
        int id = rep * 256 + tid;        // 0..1023
        int row = id >> 3, c = id & 7;
        uint32_t so = SW128((uint32_t)(row * 128 + c * 16));
        CP_ASYNC16(stage + so, Aseg + (size_t)(bm + row) * Dq + kin + c * 8);
        CP_ASYNC16(stage + 16384 + so, Bseg + (size_t)(bn + row) * Dq + kin + c * 8);
    }
}

template<int MODE>
__global__ void __launch_bounds__(256, 1)
gemm_hmma(const __half* __restrict__ Ah, const __half* __restrict__ Al,
          const __half* __restrict__ B,
          float* __restrict__ C, __half* __restrict__ gH,
          __half* __restrict__ gL, const float* __restrict__ extra) {
    extern __shared__ char sm[];
    const uint32_t smb = smem_u32(sm);
    float* sextra = (float*)(sm + 4 * G_STAGE);
    const int tid = threadIdx.x;
    const int warp = tid >> 5, lane = tid & 31;
    const int wm = warp >> 1, wn = warp & 1;
    const int bm = blockIdx.y * 128, bn = blockIdx.x * 128;

    if (tid < 128) {
        if (MODE == 0) {
            int c = bn + tid;
            sextra[tid] = extra[((c >> 6) * 2 + (bm >> 10)) * 64 + (c & 63)];
        } else {
            sextra[tid] = extra[bn + tid];
        }
    }

    const __half* Asegs[2] = {Ah, Al};

    float acc[2][8][4];
#pragma unroll
    for (int mt = 0; mt < 2; mt++)
#pragma unroll
        for (int nt = 0; nt < 8; nt++)
#pragma unroll
            for (int i = 0; i < 4; i++) acc[mt][nt][i] = 0.0f;

    uint32_t a_off[2], b_off[4];
#pragma unroll
    for (int mt = 0; mt < 2; mt++) {
        int row = wm * 32 + mt * 16 + (lane & 15);
        a_off[mt] = (uint32_t)(row * 128 + (lane >> 4) * 16);
    }
#pragma unroll
    for (int np = 0; np < 4; np++) {
        int n = wn * 64 + np * 16 + (lane >> 4) * 8 + (lane & 7);
        b_off[np] = (uint32_t)(n * 128 + ((lane >> 3) & 1) * 16);
    }

#pragma unroll
    for (int s = 0; s < 3; s++) {
        load_tile(smb + s * G_STAGE, Asegs[s >> 4], B, bm, bn, (s & 15) * 64, tid);
        CP_COMMIT();
    }

    for (int kt = 0; kt < NKT; kt++) {
        CP_WAIT(2);
        __syncthreads();
        if (kt + 3 < NKT) {
            int pk = kt + 3;
            load_tile(smb + (pk & 3) * G_STAGE, Asegs[pk >> 4], B,
                      bm, bn, (pk & 15) * 64, tid);
        }
        CP_COMMIT();

        const uint32_t sA = smb + (kt & 3) * G_STAGE;
        const uint32_t sB = sA + 16384;

        // fragment double-buffer across ks
        uint32_t af[2][2][4], bf[2][4][4];
        ldsm_x4(af[0][0], sA + SW128(a_off[0]));
        ldsm_x4(af[0][1], sA + SW128(a_off[1]));
#pragma unroll
        for (int np = 0; np < 4; np++)
            ldsm_x4(bf[0][np], sB + SW128(b_off[np]));
#pragma unroll
        for (int ks = 0; ks < 4; ks++) {
            const int cur = ks & 1, nxt = cur ^ 1;
            if (ks < 3) {
                const uint32_t ko = (uint32_t)((ks + 1) * 32);
                ldsm_x4(af[nxt][0], sA + SW128(a_off[0] + ko));
                ldsm_x4(af[nxt][1], sA + SW128(a_off[1] + ko));
#pragma unroll
                for (int np = 0; np < 4; np++)
                    ldsm_x4(bf[nxt][np], sB + SW128(b_off[np] + ko));
            }
#pragma unroll
            for (int mt = 0; mt < 2; mt++)
#pragma unroll
                for (int np = 0; np < 4; np++) {
                    mma16816(acc[mt][np * 2],     af[cur][mt], &bf[cur][np][0]);
                    mma16816(acc[mt][np * 2 + 1], af[cur][mt], &bf[cur][np][2]);
                }
        }
    }

    // Epilogue
#pragma unroll
    for (int mt = 0; mt < 2; mt++) {
        int row = bm + wm * 32 + mt * 16 + (lane >> 2);
#pragma unroll
        for (int nt = 0; nt < 8; nt++) {
            int col = bn + wn * 64 + nt * 8 + (lane & 3) * 2;
            float b0 = sextra[col - bn], b1 = sextra[col - bn + 1];
            if (MODE == 1) {
                *(float2*)&C[(size_t)row * Dq + col] =
                    make_float2(acc[mt][nt][0] + b0, acc[mt][nt][1] + b1);
                *(float2*)&C[(size_t)(row + 8) * Dq + col] =
                    make_float2(acc[mt][nt][2] + b0, acc[mt][nt][3] + b1);
            } else {
                float g0 = gelu_exact(acc[mt][nt][0] + b0);
                float g1 = gelu_exact(acc[mt][nt][1] + b1);
                float g2 = gelu_exact(acc[mt][nt][2] + b0);
                float g3 = gelu_exact(acc[mt][nt][3] + b1);
                __half h0 = __float2half_rn(g0), h1 = __float2half_rn(g1);
                __half h2 = __float2half_rn(g2), h3 = __float2half_rn(g3);
                __half2 p;
                size_t o0 = (size_t)row * Dq + col, o1 = (size_t)(row + 8) * Dq + col;
                p.x = h0; p.y = h1; *(__half2*)&gH[o0] = p;
                p.x = h2; p.y = h3; *(__half2*)&gH[o1] = p;
                p.x = __float2half_rn(g0 - __half2float(h0));
                p.y = __float2half_rn(g1 - __half2float(h1));
                *(__half2*)&gL[o0] = p;
                p.x = __float2half_rn(g2 - __half2float(h2));
                p.y = __float2half_rn(g3 - __half2float(h3));
                *(__half2*)&gL[o1] = p;
            }
        }
    }
}

// ---------------------------------------------------------------------------
extern "C" void kernel_launch(void* const* d_in, const int* in_sizes, int n_in,
                              void* d_out, int out_size) {
    const float* h_in     = (const float*)d_in[0];
    const int*   prev_idx = (const int*)d_in[1];
    // d_in[2..9] = fw/bw encoder weights: dead (softmax of broadcast scalar
    // logit is uniform), never read.
    const float* Wv    = (const float*)d_in[10];
    const float* fu_W1 = (const float*)d_in[11];
    const float* fu_b1 = (const float*)d_in[12];
    const float* fu_W2 = (const float*)d_in[13];
    const float* fu_b2 = (const float*)d_in[14];
    const float* Wo    = (const float*)d_in[15];
    const float* chain_ratio = (const float*)d_in[16];
    float* out = (float*)d_out;

    cudaFuncSetAttribute(gemm_hmma<0>, cudaFuncAttributeMaxDynamicSharedMemorySize, G_SMEM);
    cudaFuncSetAttribute(gemm_hmma<1>, cudaFuncAttributeMaxDynamicSharedMemorySize, G_SMEM);

    __half *Ah, *Al, *Wx, *Wy, *gH, *gL;
    float *beff, *outbias;
    cudaGetSymbolAddress((void**)&Ah, g_Ah);
    cudaGetSymbolAddress((void**)&Al, g_Al);
    cudaGetSymbolAddress((void**)&Wx, g_Wx);
    cudaGetSymbolAddress((void**)&Wy, g_Wy);
    cudaGetSymbolAddress((void**)&gH, g_gH);
    cudaGetSymbolAddress((void**)&gL, g_gL);
    cudaGetSymbolAddress((void**)&beff,    g_beff);
    cudaGetSymbolAddress((void**)&outbias, g_outbias);

    dim3 grid(Dq / 128, ROWS / 128);

    // 1) split h to fp16 hi/lo + per-rowblock column sums + tail outputs
    cvt_all<<<520, 256>>>((const float4*)h_in, prev_idx, chain_ratio, out);

    // 2) all small precomputations: hbar reduce, beff, Weff, Weff2, outbias
    prep2<<<448, 256>>>(Wv, fu_W1, fu_b1, fu_W2, fu_b2, Wo);

    // 3) g = GELU(h @ Weff^T + beff) -> fp16 hi/lo
    gemm_hmma<0><<<grid, 256, G_SMEM>>>(Ah, Al, Wx, nullptr, gH, gL, beff);

    // 4) out = g @ Weff2^T + outbias
    gemm_hmma<1><<<grid, 256, G_SMEM>>>(gH, gL, Wy, out, nullptr, nullptr, outbias);
}

// round 14
// speedup vs baseline: 2.4507x; 1.2946x over previous
#include <cuda_runtime.h>
#include <cuda_fp16.h>
#include <math.h>
#include <stdint.h>

// Problem constants
#define Dq   1024
#define Hh   16
#define HDq  64
#define Bq   2
#define Nq   1024
#define ROWS (Bq * Nq)          // 2048
#define OUT_FINAL (ROWS * Dq)   // 2097152

// ---------------------------------------------------------------------------
// Scratch (device globals — no allocation allowed)
// ---------------------------------------------------------------------------
__device__ float g_part[128 * Dq];                // per-rowblock column sums of h
__device__ float g_beff[Hh * Bq * HDq];           // effective layer-1 bias
__device__ float g_outbias[Dq];                   // Wo @ b2
__device__ __half g_Ah[ROWS * Dq];                // h (fp16)
__device__ __half g_Wx[Dq * Dq];                  // Weff  = W1a·Wv (fp16)
__device__ __half g_Wy[Dq * Dq];                  // Weff2 = Wo·bd(W2) (fp16)
__device__ __half g_gH[ROWS * Dq];                // GELU output (fp16)

// ---------------------------------------------------------------------------
// Helpers (base-target instructions only: ldmatrix / mma.sync / cp.async)
// ---------------------------------------------------------------------------
__device__ __forceinline__ uint32_t smem_u32(const void* p) {
    uint32_t a;
    asm("{ .reg .u64 t; cvta.to.shared.u64 t, %1; cvt.u32.u64 %0, t; }"
        : "=r"(a) : "l"(p));
    return a;
}
#define SW128(o) ((o) ^ (((o) >> 3) & 0x70))

#define CP_ASYNC16(dst, src) \
    asm volatile("cp.async.cg.shared.global [%0], [%1], 16;" :: "r"(dst), "l"(src))
#define CP_COMMIT() asm volatile("cp.async.commit_group;")
#define CP_WAIT(n)  asm volatile("cp.async.wait_group %0;" :: "n"(n) : "memory")

__device__ __forceinline__ void ldsm_x4(uint32_t* r, uint32_t addr) {
    asm volatile("ldmatrix.sync.aligned.m8n8.x4.shared.b16 {%0,%1,%2,%3}, [%4];"
                 : "=r"(r[0]), "=r"(r[1]), "=r"(r[2]), "=r"(r[3]) : "r"(addr));
}

__device__ __forceinline__ void mma16816(float* c, const uint32_t* a, const uint32_t* b) {
    asm volatile(
        "mma.sync.aligned.m16n8k16.row.col.f32.f16.f16.f32 "
        "{%0,%1,%2,%3}, {%4,%5,%6,%7}, {%8,%9}, {%0,%1,%2,%3};"
        : "+f"(c[0]), "+f"(c[1]), "+f"(c[2]), "+f"(c[3])
        : "r"(a[0]), "r"(a[1]), "r"(a[2]), "r"(a[3]), "r"(b[0]), "r"(b[1]));
}

__device__ __forceinline__ void store4h(float4 v, __half* hi, size_t i2) {
    __half2 p;
    p.x = __float2half_rn(v.x); p.y = __float2half_rn(v.y);
    ((__half2*)hi)[i2] = p;
    p.x = __float2half_rn(v.z); p.y = __float2half_rn(v.w);
    ((__half2*)hi)[i2 + 1] = p;
}

__device__ __forceinline__ float gelu_exact(float x) {
    return 0.5f * x * (1.0f + erff(x * 0.70710678118654752f));
}

// ---------------------------------------------------------------------------
// cvt_all: blocks [0,512): h -> fp16 AND write per-rowblock column partial
//          sums to g_part (block = 16 rows x 256 cols, no atomics).
//          blocks [512,520): tail outputs (targets + strength).
// ---------------------------------------------------------------------------
__global__ void __launch_bounds__(256)
cvt_all(const float4* __restrict__ hx, const int* __restrict__ prev_idx,
        const float* __restrict__ chain_ratio, float* __restrict__ out) {
    int blk = blockIdx.x, tid = threadIdx.x;
    if (blk < 512) {
        __shared__ float4 s[256];           // [rg][c4]
        int br = blk >> 2, bc = blk & 3;    // 128 row-blocks x 4 col-blocks
        int rg = tid >> 6, c4 = tid & 63;   // 4 row-groups x 64 float4-cols
        int col4 = bc * 64 + c4;            // float4 column index (0..255)
        float4 sum = make_float4(0.f, 0.f, 0.f, 0.f);
#pragma unroll
        for (int rr = 0; rr < 4; rr++) {
            int row = br * 16 + rg * 4 + rr;
            size_t idx = (size_t)row * 256 + col4;
            float4 v = hx[idx];
            store4h(v, g_Ah, idx * 2);
            sum.x += v.x; sum.y += v.y; sum.z += v.z; sum.w += v.w;
        }
        s[rg * 64 + c4] = sum;
        __syncthreads();
        if (tid < 64) {
            float4 a = s[tid], b2 = s[64 + tid], c = s[128 + tid], d = s[192 + tid];
            float4 t = make_float4(a.x + b2.x + c.x + d.x, a.y + b2.y + c.y + d.y,
                                   a.z + b2.z + c.z + d.z, a.w + b2.w + c.w + d.w);
            *(float4*)&g_part[br * Dq + bc * 256 + tid * 4] = t;
        }
    } else {
        int idx = (blk - 512) * 256 + tid;
        if (idx >= ROWS) return;
        int n = idx & (Nq - 1);
        float cr = *chain_ratio;
        float thr = floorf((float)Nq / (1.0f + expf(-cr)));
        int p = prev_idx[idx];
        p = min(max(p, 0), Nq - 1);
        float ft = ((float)n >= thr) ? (float)p : 511.0f;
        out[OUT_FINAL + idx] = ft;
        out[OUT_FINAL + ROWS + idx] = 511.0f;
        out[OUT_FINAL + 2 * ROWS + idx] = 1.0f - logf(1.0f / (float)Nq + 1e-8f);
    }
}

// ---------------------------------------------------------------------------
// prep2: all small precomputations (grid = 448 blocks x 256 threads)
//  [0,32)    : (h,b) -> hbar (reduce g_part); mu = Wv@hbar; beff = b1+(W1b+W1c)@mu
//  [32,160)  : Weff  = W1a·Wv   (per head, 128-col chunks) -> fp16
//  [160,416) : Weff2 = Wo·blockdiag(W2) (per head, 64-row chunks) -> fp16
//  [416,448) : outbias = Wo @ b2
// ---------------------------------------------------------------------------
__global__ void __launch_bounds__(256)
prep2(const float* __restrict__ Wv, const float* __restrict__ fu_W1,
      const float* __restrict__ fu_b1, const float* __restrict__ fu_W2,
      const float* __restrict__ fu_b2, const float* __restrict__ Wo) {
    __shared__ float s1[8192];   // 32KB
    __shared__ float s2[4096];   // 16KB
    const int blk = blockIdx.x, t = threadIdx.x;

    if (blk < 32) {
        // ---- hbar + mu + beff ----
        const int h = blk >> 1, b = blk & 1;
        float* hbar_s = s1;          // 1024
        float* part = s2;            // 256
        float* mu_s = s2 + 256;      // 64
        const float inv = 1.0f / (float)Nq;
        for (int k = t; k < 1024; k += 256) {
            float s = 0.0f;
#pragma unroll 8
            for (int br = 0; br < 64; br++)
                s += g_part[(b * 64 + br) * Dq + k];
            hbar_s[k] = s * inv;
        }
        __syncthreads();
        {
            int ep = t & 63, q = t >> 6;
            const float* wr = Wv + ((size_t)(h * 64 + ep)) * Dq + q * 256;
            float p = 0.0f;
#pragma unroll 8
            for (int i = 0; i < 256; i++) p = fmaf(wr[i], hbar_s[q * 256 + i], p);
            part[q * 64 + ep] = p;
        }
        __syncthreads();
        if (t < 64) mu_s[t] = part[t] + part[64 + t] + part[128 + t] + part[192 + t];
        __syncthreads();
        if (t < 64) {
            const float* w = fu_W1 + ((size_t)(h * 64 + t)) * 192;
            float acc = fu_b1[h * 64 + t];
#pragma unroll 8
            for (int e2 = 0; e2 < 64; e2++)
                acc = fmaf(w[64 + e2] + w[128 + e2], mu_s[e2], acc);
            g_beff[blk * 64 + t] = acc;
        }
    } else if (blk < 160) {
        // ---- Weff = W1a @ Wv  (rows (h,e), cols d) -> fp16 ----
        const int id = blk - 32, h = id >> 3, ch = id & 7;
        float* Wv_s = s1;    // [64][128]
        float* W1a_s = s2;   // [64][64]
#pragma unroll
        for (int k = 0; k < 4; k++) {
            int i4 = t + k * 256;
            int e = i4 >> 4, e4 = (i4 & 15) * 4;
            *(float4*)&W1a_s[e * 64 + e4] =
                *(const float4*)&fu_W1[((size_t)(h * 64 + e)) * 192 + e4];
        }
#pragma unroll
        for (int k = 0; k < 8; k++) {
            int i4 = t + k * 256;
            int e2 = i4 >> 5, d4 = (i4 & 31) * 4;
            *(float4*)&Wv_s[e2 * 128 + d4] =
                *(const float4*)&Wv[((size_t)(h * 64 + e2)) * Dq + ch * 128 + d4];
        }
        __syncthreads();
        const int d4 = (t & 31) * 4, e0 = (t >> 5) * 8;
#pragma unroll
        for (int e = e0; e < e0 + 8; e++) {
            float4 acc = make_float4(0.f, 0.f, 0.f, 0.f);
#pragma unroll 8
            for (int e2 = 0; e2 < 64; e2++) {
                float w = W1a_s[e * 64 + e2];
                float4 v = *(const float4*)&Wv_s[e2 * 128 + d4];
                acc.x = fmaf(w, v.x, acc.x); acc.y = fmaf(w, v.y, acc.y);
                acc.z = fmaf(w, v.z, acc.z); acc.w = fmaf(w, v.w, acc.w);
            }
            size_t off = ((size_t)(h * 64 + e)) * Dq + ch * 128 + d4;
            store4h(acc, g_Wx, off >> 1);
        }
    } else if (blk < 416) {
        // ---- Weff2[e, h*64+x] = sum_f Wo[e, h*64+f] * W2[h][f,x] -> fp16 ----
        const int id = blk - 160, h = id >> 4, rch = id & 15;
        float* Wo_s = s1;   // [64 e][64 f]
        float* W2_s = s2;   // [64 f][64 x]
#pragma unroll
        for (int k = 0; k < 4; k++) {
            int i4 = t + k * 256;
            int e = i4 >> 4, f4 = (i4 & 15) * 4;
            *(float4*)&Wo_s[e * 64 + f4] =
                *(const float4*)&Wo[((size_t)(rch * 64 + e)) * Dq + h * 64 + f4];
            *(float4*)&W2_s[e * 64 + f4] =
                *(const float4*)&fu_W2[((size_t)(h * 64 + e)) * 64 + f4];
        }
        __syncthreads();
        const int x4 = (t & 15) * 4, e0 = (t >> 4) * 4;
#pragma unroll
        for (int e = e0; e < e0 + 4; e++) {
            float4 acc = make_float4(0.f, 0.f, 0.f, 0.f);
#pragma unroll 8
            for (int f = 0; f < 64; f++) {
                float w = Wo_s[e * 64 + f];
                float4 v = *(const float4*)&W2_s[f * 64 + x4];
                acc.x = fmaf(w, v.x, acc.x); acc.y = fmaf(w, v.y, acc.y);
                acc.z = fmaf(w, v.z, acc.z); acc.w = fmaf(w, v.w, acc.w);
            }
            size_t off = ((size_t)(rch * 64 + e)) * Dq + h * 64 + x4;
            store4h(acc, g_Wy, off >> 1);
        }
    } else {
        // ---- outbias = Wo @ b2 ----
        const int id = blk - 416;     // 0..31, 32 e-rows each
        float* b2s = s1;
        for (int k = t; k < 1024; k += 256) b2s[k] = fu_b2[k];
        __syncthreads();
        int e = id * 32 + (t >> 3), seg = t & 7;
        const float* wr = Wo + (size_t)e * Dq + seg * 128;
        float p = 0.0f;
#pragma unroll 8
        for (int i = 0; i < 128; i++) p = fmaf(wr[i], b2s[seg * 128 + i], p);
        p += __shfl_down_sync(0xFFFFFFFFu, p, 4, 8);
        p += __shfl_down_sync(0xFFFFFFFFu, p, 2, 8);
        p += __shfl_down_sync(0xFFFFFFFFu, p, 1, 8);
        if (seg == 0) g_outbias[e] = p;
    }
}

// ---------------------------------------------------------------------------
// HMMA fp16 GEMM: C[2048,1024] = A[2048,1024] @ B[1024,1024]^T (K=1024).
// CTA tile 128x128, BK=64, 256 thr (8 warps, 4x2 grid, 32x64 warp tiles),
// 4-stage cp.async pipeline (wait_group 2) + intra-kt fragment double-buffer.
// MODE 0: epilogue x+beff -> GELU -> fp16 (gH).   extra = beff
// MODE 1: epilogue +bias -> fp32 C.               extra = outbias
// ---------------------------------------------------------------------------
#define G_STAGE 32768
#define G_SMEM  (4 * G_STAGE + 512)
#define NKT 16

__device__ __forceinline__ void load_tile(uint32_t stage,
                                          const __half* __restrict__ A,
                                          const __half* __restrict__ B,
                                          int bm, int bn, int kin, int tid) {
#pragma unroll
    for (int rep = 0; rep < 4; rep++) {
        int id = rep * 256 + tid;        // 0..1023
        int row = id >> 3, c = id & 7;
        uint32_t so = SW128((uint32_t)(row * 128 + c * 16));
        CP_ASYNC16(stage + so, A + (size_t)(bm + row) * Dq + kin + c * 8);
        CP_ASYNC16(stage + 16384 + so, B + (size_t)(bn + row) * Dq + kin + c * 8);
    }
}

template<int MODE>
__global__ void __launch_bounds__(256, 1)
gemm_hmma(const __half* __restrict__ A, const __half* __restrict__ B,
          float* __restrict__ C, __half* __restrict__ gH,
          const float* __restrict__ extra) {
    extern __shared__ char sm[];
    const uint32_t smb = smem_u32(sm);
    float* sextra = (float*)(sm + 4 * G_STAGE);
    const int tid = threadIdx.x;
    const int warp = tid >> 5, lane = tid & 31;
    const int wm = warp >> 1, wn = warp & 1;
    const int bm = blockIdx.y * 128, bn = blockIdx.x * 128;

    if (tid < 128) {
        if (MODE == 0) {
            int c = bn + tid;
            sextra[tid] = extra[((c >> 6) * 2 + (bm >> 10)) * 64 + (c & 63)];
        } else {
            sextra[tid] = extra[bn + tid];
        }
    }

    float acc[2][8][4];
#pragma unroll
    for (int mt = 0; mt < 2; mt++)
#pragma unroll
        for (int nt = 0; nt < 8; nt++)
#pragma unroll
            for (int i = 0; i < 4; i++) acc[mt][nt][i] = 0.0f;

    uint32_t a_off[2], b_off[4];
#pragma unroll
    for (int mt = 0; mt < 2; mt++) {
        int row = wm * 32 + mt * 16 + (lane & 15);
        a_off[mt] = (uint32_t)(row * 128 + (lane >> 4) * 16);
    }
#pragma unroll
    for (int np = 0; np < 4; np++) {
        int n = wn * 64 + np * 16 + (lane >> 4) * 8 + (lane & 7);
        b_off[np] = (uint32_t)(n * 128 + ((lane >> 3) & 1) * 16);
    }

#pragma unroll
    for (int s = 0; s < 3; s++) {
        load_tile(smb + s * G_STAGE, A, B, bm, bn, s * 64, tid);
        CP_COMMIT();
    }

    for (int kt = 0; kt < NKT; kt++) {
        CP_WAIT(2);
        __syncthreads();
        if (kt + 3 < NKT) {
            int pk = kt + 3;
            load_tile(smb + (pk & 3) * G_STAGE, A, B, bm, bn, pk * 64, tid);
        }
        CP_COMMIT();

        const uint32_t sA = smb + (kt & 3) * G_STAGE;
        const uint32_t sB = sA + 16384;

        // fragment double-buffer across ks
        uint32_t af[2][2][4], bf[2][4][4];
        ldsm_x4(af[0][0], sA + SW128(a_off[0]));
        ldsm_x4(af[0][1], sA + SW128(a_off[1]));
#pragma unroll
        for (int np = 0; np < 4; np++)
            ldsm_x4(bf[0][np], sB + SW128(b_off[np]));
#pragma unroll
        for (int ks = 0; ks < 4; ks++) {
            const int cur = ks & 1, nxt = cur ^ 1;
            if (ks < 3) {
                const uint32_t ko = (uint32_t)((ks + 1) * 32);
                ldsm_x4(af[nxt][0], sA + SW128(a_off[0] + ko));
                ldsm_x4(af[nxt][1], sA + SW128(a_off[1] + ko));
#pragma unroll
                for (int np = 0; np < 4; np++)
                    ldsm_x4(bf[nxt][np], sB + SW128(b_off[np] + ko));
            }
#pragma unroll
            for (int mt = 0; mt < 2; mt++)
#pragma unroll
                for (int np = 0; np < 4; np++) {
                    mma16816(acc[mt][np * 2],     af[cur][mt], &bf[cur][np][0]);
                    mma16816(acc[mt][np * 2 + 1], af[cur][mt], &bf[cur][np][2]);
                }
        }
    }

    // Epilogue
#pragma unroll
    for (int mt = 0; mt < 2; mt++) {
        int row = bm + wm * 32 + mt * 16 + (lane >> 2);
#pragma unroll
        for (int nt = 0; nt < 8; nt++) {
            int col = bn + wn * 64 + nt * 8 + (lane & 3) * 2;
            float b0 = sextra[col - bn], b1 = sextra[col - bn + 1];
            if (MODE == 1) {
                *(float2*)&C[(size_t)row * Dq + col] =
                    make_float2(acc[mt][nt][0] + b0, acc[mt][nt][1] + b1);
                *(float2*)&C[(size_t)(row + 8) * Dq + col] =
                    make_float2(acc[mt][nt][2] + b0, acc[mt][nt][3] + b1);
            } else {
                float g0 = gelu_exact(acc[mt][nt][0] + b0);
                float g1 = gelu_exact(acc[mt][nt][1] + b1);
                float g2 = gelu_exact(acc[mt][nt][2] + b0);
                float g3 = gelu_exact(acc[mt][nt][3] + b1);
                __half2 p;
                size_t o0 = (size_t)row * Dq + col, o1 = (size_t)(row + 8) * Dq + col;
                p.x = __float2half_rn(g0); p.y = __float2half_rn(g1);
                *(__half2*)&gH[o0] = p;
                p.x = __float2half_rn(g2); p.y = __float2half_rn(g3);
                *(__half2*)&gH[o1] = p;
            }
        }
    }
}

// ---------------------------------------------------------------------------
extern "C" void kernel_launch(void* const* d_in, const int* in_sizes, int n_in,
                              void* d_out, int out_size) {
    const float* h_in     = (const float*)d_in[0];
    const int*   prev_idx = (const int*)d_in[1];
    // d_in[2..9] = fw/bw encoder weights: dead (softmax of broadcast scalar
    // logit is uniform), never read.
    const float* Wv    = (const float*)d_in[10];
    const float* fu_W1 = (const float*)d_in[11];
    const float* fu_b1 = (const float*)d_in[12];
    const float* fu_W2 = (const float*)d_in[13];
    const float* fu_b2 = (const float*)d_in[14];
    const float* Wo    = (const float*)d_in[15];
    const float* chain_ratio = (const float*)d_in[16];
    float* out = (float*)d_out;

    cudaFuncSetAttribute(gemm_hmma<0>, cudaFuncAttributeMaxDynamicSharedMemorySize, G_SMEM);
    cudaFuncSetAttribute(gemm_hmma<1>, cudaFuncAttributeMaxDynamicSharedMemorySize, G_SMEM);

    __half *Ah, *Wx, *Wy, *gH;
    float *beff, *outbias;
    cudaGetSymbolAddress((void**)&Ah, g_Ah);
    cudaGetSymbolAddress((void**)&Wx, g_Wx);
    cudaGetSymbolAddress((void**)&Wy, g_Wy);
    cudaGetSymbolAddress((void**)&gH, g_gH);
    cudaGetSymbolAddress((void**)&beff,    g_beff);
    cudaGetSymbolAddress((void**)&outbias, g_outbias);

    dim3 grid(Dq / 128, ROWS / 128);

    // 1) h -> fp16 + per-rowblock column sums + tail outputs
    cvt_all<<<520, 256>>>((const float4*)h_in, prev_idx, chain_ratio, out);

    // 2) all small precomputations: hbar reduce, beff, Weff, Weff2, outbias
    prep2<<<448, 256>>>(Wv, fu_W1, fu_b1, fu_W2, fu_b2, Wo);

    // 3) g = GELU(h @ Weff^T + beff) -> fp16
    gemm_hmma<0><<<grid, 256, G_SMEM>>>(Ah, Wx, nullptr, gH, beff);

    // 4) out = g @ Weff2^T + outbias
    gemm_hmma<1><<<grid, 256, G_SMEM>>>(gH, Wy, out, nullptr, outbias);
}